// round 16
// baseline (speedup 1.0000x reference)
#include <cuda_runtime.h>
#include <cuda_bf16.h>
#include <math.h>
#include <stdint.h>

#define N_NODES 100000
#define F_IN    256
#define HID     128
#define CLS     32
#define E_MAX   1600000
#define EPS_F   0.1f
#define GAMMA_F 0.1f

// ---------------------------------------------------------------------------
// Scratch (device globals -- no allocation allowed; zero-initialized at load)
// ---------------------------------------------------------------------------
__device__ __align__(16) int      g_degi [N_NODES];   // INVARIANT: zero at entry of every launch
__device__ __align__(16) int      g_bsum [128];
__device__            volatile int g_ready;
__device__            int          g_done;
__device__ __align__(16) int      g_off  [N_NODES + 1];
__device__ __align__(16) int      g_cur  [N_NODES];
__device__ __align__(16) int      g_csr  [E_MAX];
__device__ __align__(16) float    g_dinv [N_NODES];
__device__ __align__(16) float    g_h1   [(size_t)N_NODES * HID];
__device__ __align__(16) uint32_t g_xw1b [(size_t)N_NODES * HID / 2];  // bf16x2
__device__ __align__(16) uint32_t g_z1b  [(size_t)N_NODES * HID / 2];  // bf16x2
__device__ __align__(16) float    g_h2   [(size_t)N_NODES * CLS];
__device__ __align__(16) uint32_t g_xw2b [(size_t)N_NODES * CLS / 2];  // bf16x2
__device__ __align__(16) float    g_z2   [(size_t)N_NODES * CLS];
__device__ __align__(16) float    g_comb1[2 * HID * HID];
__device__ __align__(16) float    g_comb2[2 * CLS * CLS];

// ---------------------------------------------------------------------------
// Prep + degree accumulate in ONE launch.
//   [0, HID*HID)              : comb1 build
//   [HID*HID, +CLS*CLS)       : comb2 build
//   [PREP_EDGE_OFF, +E)       : degree atomics (g_degi starts zero -- invariant)
// ---------------------------------------------------------------------------
#define PREP_C2_OFF   (HID * HID)
#define PREP_EDGE_OFF (PREP_C2_OFF + CLS * CLS)

__global__ void k_prepdeg(const float* __restrict__ W1, const float* __restrict__ phi1,
                          const float* __restrict__ W2, const float* __restrict__ phi2,
                          const int* __restrict__ col, int E) {
    int i = blockIdx.x * blockDim.x + threadIdx.x;
    if (i < HID * HID) {
        int r = i / HID, c = i % HID;
        g_comb1[r * HID + c] = phi1[i];
        g_comb1[(HID + r) * HID + c] = W1[r * HID + c] - W1[c * HID + r] - ((r == c) ? GAMMA_F : 0.0f);
    } else if (i < PREP_EDGE_OFF) {
        int j = i - PREP_C2_OFF;
        int r = j / CLS, c = j % CLS;
        g_comb2[r * CLS + c] = phi2[j];
        g_comb2[(CLS + r) * CLS + c] = W2[r * CLS + c] - W2[c * CLS + r] - ((r == c) ? GAMMA_F : 0.0f);
    } else {
        int e = i - PREP_EDGE_OFF;
        if (e < E) atomicAdd(&g_degi[col[e]], 1);
    }
}

// ---------------------------------------------------------------------------
// Single-pass scan: block scan + publish/spin barrier + prefix + finalize.
//   Writes g_off/g_cur/g_dinv, re-zeroes g_degi (restores invariant),
//   self-resets barrier counters via done-counter.
//   Grid: 98 blocks x 1024 -- all co-resident on 148 SMs (no deadlock).
// ---------------------------------------------------------------------------
__global__ void k_scan(int n) {
    __shared__ int sh[1024];
    __shared__ int red[128];
    const int b = blockIdx.x, t = threadIdx.x;
    const int i = b * 1024 + t;
    const int nb = gridDim.x;

    int d = (i < n) ? g_degi[i] : 0;
    sh[t] = d;
    __syncthreads();
    for (int o = 1; o < 1024; o <<= 1) {
        int v = (t >= o) ? sh[t - o] : 0;
        __syncthreads();
        sh[t] += v;
        __syncthreads();
    }

    // publish block sum
    if (t == 1023) {
        g_bsum[b] = sh[1023];
        __threadfence();
        atomicAdd((int*)&g_ready, 1);
    }

    // spin until all blocks published
    if (t == 0) {
        while (g_ready < nb) { }
        __threadfence();
    }
    __syncthreads();

    // prefix of block sums (nb <= 128)
    red[t & 127] = 0;  // only threads <128 matter; harmless overwrite pattern
    __syncthreads();
    if (t < 128) red[t] = (t < b && t < nb) ? g_bsum[t] : 0;
    __syncthreads();
    for (int o = 64; o > 0; o >>= 1) {
        if (t < o) red[t] += red[t + o];
        __syncthreads();
    }
    int add = red[0];

    if (i < n) {
        int inc = sh[t] + add;
        int off = inc - d;
        g_off[i] = off;
        g_cur[i] = off;
        g_dinv[i] = rsqrtf((float)d + 1.0f);
        g_degi[i] = 0;                 // restore zero-invariant for next launch
        if (i == n - 1) g_off[n] = inc;
    }

    // reset barrier counters (last block to finish)
    __syncthreads();
    if (t == 0) {
        int done = atomicAdd(&g_done, 1);
        if (done == nb - 1) { g_ready = 0; g_done = 0; __threadfence(); }
    }
}

__global__ void k_place(const int* __restrict__ row, const int* __restrict__ col, int E) {
    int e = blockIdx.x * blockDim.x + threadIdx.x;
    if (e >= E) return;
    int c = col[e];
    int p = atomicAdd(&g_cur[c], 1);
    g_csr[p] = row[e];
}

// ---------------------------------------------------------------------------
// MMA helpers
// ---------------------------------------------------------------------------
__device__ __forceinline__ void mma_bf16(float c[4], const uint32_t a[4], const uint32_t b[2]) {
    asm("mma.sync.aligned.m16n8k16.row.col.f32.bf16.bf16.f32 "
        "{%0,%1,%2,%3}, {%4,%5,%6,%7}, {%8,%9}, {%0,%1,%2,%3};"
        : "+f"(c[0]), "+f"(c[1]), "+f"(c[2]), "+f"(c[3])
        : "r"(a[0]), "r"(a[1]), "r"(a[2]), "r"(a[3]), "r"(b[0]), "r"(b[1]));
}
__device__ __forceinline__ uint32_t pack_bf2(float x, float y) {
    __nv_bfloat162 p = __float22bfloat162_rn(make_float2(x, y));
    return *reinterpret_cast<uint32_t*>(&p);
}

// ---------------------------------------------------------------------------
// bf16 MMA GEMM (m16n8k16), 256 threads, register-prefetch double buffering.
//   MODE 0: C (f32) = v (+bias)(+relu)
//   MODE 1: gc<D: Cb (bf16x2) = dinv*v ; else C2 (z, f32) = v
//   MODE 2: gc<D: Cb (bf16x2) = dinv*v ; else (uint32_t*)C2 (z, bf16x2) = v
// ---------------------------------------------------------------------------
template<int BN, int WN, int MODE, bool RELU, bool HASB>
__global__ __launch_bounds__(256) void
k_mmab(const float* __restrict__ A, const float* __restrict__ B,
       const float* __restrict__ bias,
       float* __restrict__ C, float* __restrict__ C2,
       uint32_t* __restrict__ Cb,
       int M, int Ncols, int K, int D) {
    constexpr int BM = 128, BK = 32, BKP2 = 20;
    constexpr int MT = 2, NT = WN / 8;
    constexpr int AL = (BM * BK / 4) / 256;
    constexpr int BL = (BN * BK / 4) / 256;
    __shared__ uint32_t As[BM][BKP2];
    __shared__ uint32_t Bs[BN][BKP2];

    const int tid  = threadIdx.x;
    const int warp = tid >> 5, lane = tid & 31;
    const int grp  = lane >> 2, qid = lane & 3;
    const int wm0  = (warp & 3) * 32;
    const int wn0  = (warp >> 2) * WN;
    const int row0 = blockIdx.y * BM;
    const int col0 = blockIdx.x * BN;

    const int ldr = tid >> 3;
    const int ldc = (tid & 7) * 4;
    const int pc  = (tid & 7) * 2;

    float acc[MT][NT][4];
#pragma unroll
    for (int i = 0; i < MT; i++)
#pragma unroll
        for (int j = 0; j < NT; j++)
#pragma unroll
            for (int q = 0; q < 4; q++) acc[i][j][q] = 0.0f;

    float4 pa[AL], pb[BL];

#pragma unroll
    for (int u = 0; u < AL; u++) {
        int gr = row0 + ldr + u * 32;
        pa[u] = make_float4(0.f, 0.f, 0.f, 0.f);
        if (gr < M) pa[u] = *(const float4*)(A + (size_t)gr * K + ldc);
    }
#pragma unroll
    for (int u = 0; u < BL; u++)
        pb[u] = *(const float4*)(B + (size_t)(col0 + ldr + u * 32) * K + ldc);

    for (int k0 = 0; k0 < K; k0 += BK) {
        __syncthreads();
#pragma unroll
        for (int u = 0; u < AL; u++) {
            As[ldr + u * 32][pc    ] = pack_bf2(pa[u].x, pa[u].y);
            As[ldr + u * 32][pc + 1] = pack_bf2(pa[u].z, pa[u].w);
        }
#pragma unroll
        for (int u = 0; u < BL; u++) {
            Bs[ldr + u * 32][pc    ] = pack_bf2(pb[u].x, pb[u].y);
            Bs[ldr + u * 32][pc + 1] = pack_bf2(pb[u].z, pb[u].w);
        }
        __syncthreads();

        if (k0 + BK < K) {
            int kn = k0 + BK;
#pragma unroll
            for (int u = 0; u < AL; u++) {
                int gr = row0 + ldr + u * 32;
                pa[u] = make_float4(0.f, 0.f, 0.f, 0.f);
                if (gr < M) pa[u] = *(const float4*)(A + (size_t)gr * K + kn + ldc);
            }
#pragma unroll
            for (int u = 0; u < BL; u++)
                pb[u] = *(const float4*)(B + (size_t)(col0 + ldr + u * 32) * K + kn + ldc);
        }

#pragma unroll
        for (int kk = 0; kk < BK / 16; kk++) {
            const int kb = kk * 8;
            uint32_t af[MT][4], bf[NT][2];
#pragma unroll
            for (int i = 0; i < MT; i++) {
                int m = wm0 + i * 16 + grp;
                af[i][0] = As[m    ][kb + qid];
                af[i][1] = As[m + 8][kb + qid];
                af[i][2] = As[m    ][kb + qid + 4];
                af[i][3] = As[m + 8][kb + qid + 4];
            }
#pragma unroll
            for (int j = 0; j < NT; j++) {
                int n = wn0 + j * 8 + grp;
                bf[j][0] = Bs[n][kb + qid];
                bf[j][1] = Bs[n][kb + qid + 4];
            }
#pragma unroll
            for (int i = 0; i < MT; i++)
#pragma unroll
                for (int j = 0; j < NT; j++)
                    mma_bf16(acc[i][j], af[i], bf[j]);
        }
    }

#pragma unroll
    for (int i = 0; i < MT; i++) {
#pragma unroll
        for (int h = 0; h < 2; h++) {
            int gr = row0 + wm0 + i * 16 + grp + h * 8;
            if (gr >= M) continue;
            float di = (MODE != 0) ? g_dinv[gr] : 0.0f;
#pragma unroll
            for (int j = 0; j < NT; j++) {
                int gc = col0 + wn0 + j * 8 + 2 * qid;
                float v0 = acc[i][j][2 * h];
                float v1 = acc[i][j][2 * h + 1];
                if (MODE == 0) {
                    if (HASB) { v0 += bias[gc]; v1 += bias[gc + 1]; }
                    if (RELU) { v0 = fmaxf(v0, 0.f); v1 = fmaxf(v1, 0.f); }
                    *(float2*)(C + (size_t)gr * Ncols + gc) = make_float2(v0, v1);
                } else if (MODE == 1) {
                    if (gc < D) {
                        Cb[(size_t)gr * (D / 2) + gc / 2] = pack_bf2(di * v0, di * v1);
                    } else {
                        *(float2*)(C2 + (size_t)gr * D + gc - D) = make_float2(v0, v1);
                    }
                } else {
                    if (gc < D) {
                        Cb[(size_t)gr * (D / 2) + gc / 2] = pack_bf2(di * v0, di * v1);
                    } else {
                        ((uint32_t*)C2)[(size_t)gr * (D / 2) + (gc - D) / 2] = pack_bf2(v0, v1);
                    }
                }
            }
        }
    }
}

// ---------------------------------------------------------------------------
// Layer-1 CSR gather + fused Euler update (warp/node, lane = 4 cols)
// ---------------------------------------------------------------------------
__device__ __forceinline__ void acc_bf4(float& sx, float& sy, float& sz, float& sw, uint2 v) {
    __nv_bfloat162 q0 = *reinterpret_cast<__nv_bfloat162*>(&v.x);
    __nv_bfloat162 q1 = *reinterpret_cast<__nv_bfloat162*>(&v.y);
    float2 g0 = __bfloat1622float2(q0);
    float2 g1 = __bfloat1622float2(q1);
    sx += g0.x; sy += g0.y; sz += g1.x; sw += g1.y;
}

__global__ void k_gather1(const float* __restrict__ b1) {
    int n    = (blockIdx.x * blockDim.x + threadIdx.x) >> 5;
    int lane = threadIdx.x & 31;
    if (n >= N_NODES) return;

    const uint2* xb = (const uint2*)g_xw1b;
    int beg = g_off[n], end = g_off[n + 1];

    float sx, sy, sz, sw;
    { uint2 sv = xb[(size_t)n * 32 + lane];
      sx = sy = sz = sw = 0.0f;
      acc_bf4(sx, sy, sz, sw, sv); }

    for (int base = beg; base < end; base += 32) {
        int mye = base + lane;
        int r = (mye < end) ? g_csr[mye] : 0;
        int cnt = min(32, end - base);
        int j = 0;
        for (; j + 4 <= cnt; j += 4) {
            int r0 = __shfl_sync(0xffffffffu, r, j);
            int r1 = __shfl_sync(0xffffffffu, r, j + 1);
            int r2 = __shfl_sync(0xffffffffu, r, j + 2);
            int r3 = __shfl_sync(0xffffffffu, r, j + 3);
            uint2 v0 = xb[(size_t)r0 * 32 + lane];
            uint2 v1 = xb[(size_t)r1 * 32 + lane];
            uint2 v2 = xb[(size_t)r2 * 32 + lane];
            uint2 v3 = xb[(size_t)r3 * 32 + lane];
            acc_bf4(sx, sy, sz, sw, v0);
            acc_bf4(sx, sy, sz, sw, v1);
            acc_bf4(sx, sy, sz, sw, v2);
            acc_bf4(sx, sy, sz, sw, v3);
        }
        for (; j < cnt; j++) {
            int rr = __shfl_sync(0xffffffffu, r, j);
            acc_bf4(sx, sy, sz, sw, xb[(size_t)rr * 32 + lane]);
        }
    }

    float u = g_dinv[n];
    size_t i4 = (size_t)n * 32 + lane;
    uint2 zv = ((const uint2*)g_z1b)[i4];
    float2 za = __bfloat1622float2(*reinterpret_cast<__nv_bfloat162*>(&zv.x));
    float2 zb = __bfloat1622float2(*reinterpret_cast<__nv_bfloat162*>(&zv.y));
    float4 b = ((const float4*)b1)[lane];
    float4 h = ((const float4*)g_h1)[i4];
    h.x += EPS_F * tanhf(za.x + u * sx + b.x);
    h.y += EPS_F * tanhf(za.y + u * sy + b.y);
    h.z += EPS_F * tanhf(zb.x + u * sz + b.z);
    h.w += EPS_F * tanhf(zb.y + u * sw + b.w);
    ((float4*)g_h1)[i4] = h;
}

// ---------------------------------------------------------------------------
// Layer-2 gather (bf16) + fused update + log_softmax
//   Half-warp per node, per-half-warp shfl masks.
// ---------------------------------------------------------------------------
__global__ void k_gather2(const float* __restrict__ b2, float* __restrict__ out) {
    int n = (blockIdx.x * blockDim.x + threadIdx.x) >> 4;
    int l = threadIdx.x & 15;
    if (n >= N_NODES) return;

    const unsigned hm = 0xffffu << (threadIdx.x & 16);

    int beg = g_off[n], end = g_off[n + 1];

    float s0, s1;
    { uint32_t sv = g_xw2b[(size_t)n * 16 + l];
      __nv_bfloat162 sp = *reinterpret_cast<__nv_bfloat162*>(&sv);
      float2 sf = __bfloat1622float2(sp);
      s0 = sf.x; s1 = sf.y; }

    for (int base = beg; base < end; base += 16) {
        int mye = base + l;
        int r = (mye < end) ? g_csr[mye] : 0;
        int cnt = min(16, end - base);
        int j = 0;
        for (; j + 4 <= cnt; j += 4) {
            int rr[4];
#pragma unroll
            for (int q = 0; q < 4; q++) rr[q] = __shfl_sync(hm, r, j + q, 16);
            uint32_t a[4];
#pragma unroll
            for (int q = 0; q < 4; q++) a[q] = g_xw2b[(size_t)rr[q] * 16 + l];
#pragma unroll
            for (int q = 0; q < 4; q++) {
                float2 f = __bfloat1622float2(*reinterpret_cast<__nv_bfloat162*>(&a[q]));
                s0 += f.x; s1 += f.y;
            }
        }
        for (; j < cnt; j++) {
            int rr = __shfl_sync(hm, r, j, 16);
            uint32_t a = g_xw2b[(size_t)rr * 16 + l];
            float2 f = __bfloat1622float2(*reinterpret_cast<__nv_bfloat162*>(&a));
            s0 += f.x; s1 += f.y;
        }
    }

    float u = g_dinv[n];
    size_t base2 = (size_t)n * CLS + 2 * l;
    float2 z = *(const float2*)(g_z2 + base2);
    float2 h = *(const float2*)(g_h2 + base2);
    float2 b = *(const float2*)(b2 + 2 * l);
    float v0 = h.x + EPS_F * tanhf(z.x + u * s0 + b.x);
    float v1 = h.y + EPS_F * tanhf(z.y + u * s1 + b.y);
    float m = fmaxf(v0, v1);
#pragma unroll
    for (int o = 8; o > 0; o >>= 1) m = fmaxf(m, __shfl_xor_sync(hm, m, o, 16));
    float sum = expf(v0 - m) + expf(v1 - m);
#pragma unroll
    for (int o = 8; o > 0; o >>= 1) sum += __shfl_xor_sync(hm, sum, o, 16);
    float ls = logf(sum);
    *(float2*)(out + base2) = make_float2(v0 - m - ls, v1 - m - ls);
}

// ---------------------------------------------------------------------------
// Launch (single default stream; 8 launches)
// ---------------------------------------------------------------------------
extern "C" void kernel_launch(void* const* d_in, const int* in_sizes, int n_in,
                              void* d_out, int out_size) {
    const float* x      = (const float*)d_in[0];
    const float* lin1_w = (const float*)d_in[1];
    const float* lin1_b = (const float*)d_in[2];
    const float* lin2_w = (const float*)d_in[3];
    const float* lin2_b = (const float*)d_in[4];
    const float* W1     = (const float*)d_in[5];
    const float* phi1   = (const float*)d_in[6];
    const float* b1     = (const float*)d_in[7];
    const float* W2     = (const float*)d_in[8];
    const float* phi2   = (const float*)d_in[9];
    const float* b2     = (const float*)d_in[10];
    const int*   ei     = (const int*)d_in[11];
    int E = in_sizes[11] / 2;
    const int* erow = ei;
    const int* ecol = ei + E;
    float* out = (float*)d_out;

    float *p_h1, *p_h2, *p_z2, *p_c1, *p_c2;
    uint32_t *p_xw1b, *p_z1b, *p_xw2b;
    cudaGetSymbolAddress((void**)&p_h1,   g_h1);
    cudaGetSymbolAddress((void**)&p_xw1b, g_xw1b);
    cudaGetSymbolAddress((void**)&p_z1b,  g_z1b);
    cudaGetSymbolAddress((void**)&p_h2,   g_h2);
    cudaGetSymbolAddress((void**)&p_xw2b, g_xw2b);
    cudaGetSymbolAddress((void**)&p_z2,   g_z2);
    cudaGetSymbolAddress((void**)&p_c1,   g_comb1);
    cudaGetSymbolAddress((void**)&p_c2,   g_comb2);

    const int TPB = 256;
    int mb128 = (N_NODES + 127) / 128;
    int scan_blocks = (N_NODES + 1023) / 1024;  // 98
    int warp_blocks  = (N_NODES * 32 + TPB - 1) / TPB;
    int hwarp_blocks = (N_NODES * 16 + TPB - 1) / TPB;

    // ---- prep (comb1+comb2) + degree atomics, one launch ----
    int prep_total = PREP_EDGE_OFF + E;
    k_prepdeg<<<(prep_total + TPB - 1) / TPB, TPB>>>(W1, phi1, W2, phi2, ecol, E);

    // ---- single-pass scan (off/cur/dinv; re-zeroes degi) ----
    k_scan<<<scan_blocks, 1024>>>(N_NODES);

    // ---- CSR placement ----
    k_place<<<(E + TPB - 1) / TPB, TPB>>>(erow, ecol, E);

    // ---- h1 = relu(x @ lin1_w^T + lin1_b)   [N,128]  (bf16 MMA) ----
    k_mmab<128, 64, 0, true, true>
        <<<dim3(1, mb128), 256>>>(x, lin1_w, lin1_b, p_h1, nullptr, nullptr, N_NODES, HID, F_IN, 0);

    // ---- (xws1_bf16 | z1_bf16) = h1 @ comb1^T   [N,256]  (MODE 2) ----
    k_mmab<128, 64, 2, false, false>
        <<<dim3(2, mb128), 256>>>(p_h1, p_c1, nullptr, nullptr, (float*)p_z1b, p_xw1b, N_NODES, 2 * HID, HID, HID);

    // ---- layer-1 gather + fused Euler update ----
    k_gather1<<<warp_blocks, TPB>>>(b1);

    // ---- h2 = h1 @ lin2_w^T + lin2_b   [N,32]  (bf16 MMA) ----
    k_mmab<32, 16, 0, false, true>
        <<<dim3(1, mb128), 256>>>(p_h1, lin2_w, lin2_b, p_h2, nullptr, nullptr, N_NODES, CLS, HID, 0);

    // ---- (xws2_bf16 | z2_f32) = h2 @ comb2^T   [N,64]  (MODE 1) ----
    k_mmab<64, 32, 1, false, false>
        <<<dim3(1, mb128), 256>>>(p_h2, p_c2, nullptr, nullptr, p_z2, p_xw2b, N_NODES, 2 * CLS, CLS, CLS);

    // ---- layer-2 gather + fused update + log_softmax ----
    k_gather2<<<hwarp_blocks, TPB>>>(b2, out);
}

// round 17
// speedup vs baseline: 1.0257x; 1.0257x over previous
#include <cuda_runtime.h>
#include <cuda_bf16.h>
#include <math.h>
#include <stdint.h>

#define N_NODES 100000
#define F_IN    256
#define HID     128
#define CLS     32
#define E_MAX   1600000
#define EPS_F   0.1f
#define GAMMA_F 0.1f

// ---------------------------------------------------------------------------
// Scratch (device globals -- no allocation allowed)
// ---------------------------------------------------------------------------
__device__ __align__(16) int      g_degi [N_NODES];
__device__ __align__(16) int      g_scan [N_NODES];
__device__ __align__(16) int      g_bsum [128];
__device__ __align__(16) int      g_off  [N_NODES + 1];
__device__ __align__(16) int      g_cur  [N_NODES];
__device__ __align__(16) int      g_csr  [E_MAX];
__device__ __align__(16) float    g_dinv [N_NODES];
__device__ __align__(16) float    g_h1   [(size_t)N_NODES * HID];
__device__ __align__(16) uint32_t g_xw1b [(size_t)N_NODES * HID / 2];  // bf16x2
__device__ __align__(16) uint32_t g_z1b  [(size_t)N_NODES * HID / 2];  // bf16x2
__device__ __align__(16) float    g_h2   [(size_t)N_NODES * CLS];
__device__ __align__(16) uint32_t g_xw2b [(size_t)N_NODES * CLS / 2];  // bf16x2
__device__ __align__(16) float    g_z2   [(size_t)N_NODES * CLS];
__device__ __align__(16) float    g_comb1[2 * HID * HID];
__device__ __align__(16) float    g_comb2[2 * CLS * CLS];

// ---------------------------------------------------------------------------
// Prep: comb1 + comb2 + deg zero in ONE launch
// ---------------------------------------------------------------------------
#define PREP_C2_OFF  (HID * HID)
#define PREP_DEG_OFF (PREP_C2_OFF + CLS * CLS)
#define PREP_TOTAL   (PREP_DEG_OFF + N_NODES)

__global__ void k_prep(const float* __restrict__ W1, const float* __restrict__ phi1,
                       const float* __restrict__ W2, const float* __restrict__ phi2) {
    int i = blockIdx.x * blockDim.x + threadIdx.x;
    if (i < HID * HID) {
        int r = i / HID, c = i % HID;
        g_comb1[r * HID + c] = phi1[i];
        g_comb1[(HID + r) * HID + c] = W1[r * HID + c] - W1[c * HID + r] - ((r == c) ? GAMMA_F : 0.0f);
    } else if (i < PREP_DEG_OFF) {
        int j = i - PREP_C2_OFF;
        int r = j / CLS, c = j % CLS;
        g_comb2[r * CLS + c] = phi2[j];
        g_comb2[(CLS + r) * CLS + c] = W2[r * CLS + c] - W2[c * CLS + r] - ((r == c) ? GAMMA_F : 0.0f);
    } else {
        int j = i - PREP_DEG_OFF;
        if (j < N_NODES) g_degi[j] = 0;
    }
}

// ---------------------------------------------------------------------------
// Degree accumulate / scan / CSR build
// ---------------------------------------------------------------------------
__global__ void k_deg_accum(const int* __restrict__ col, int E) {
    int e = blockIdx.x * blockDim.x + threadIdx.x;
    if (e < E) atomicAdd(&g_degi[col[e]], 1);
}
__global__ void k_scan1(int n) {
    __shared__ int sh[1024];
    int i = blockIdx.x * 1024 + threadIdx.x;
    int v = (i < n) ? g_degi[i] : 0;
    sh[threadIdx.x] = v;
    __syncthreads();
    for (int o = 1; o < 1024; o <<= 1) {
        int t = (threadIdx.x >= o) ? sh[threadIdx.x - o] : 0;
        __syncthreads();
        sh[threadIdx.x] += t;
        __syncthreads();
    }
    if (i < n) g_scan[i] = sh[threadIdx.x];
    if (threadIdx.x == 1023) g_bsum[blockIdx.x] = sh[1023];
}
__global__ void k_scan3(int n) {
    __shared__ int red[128];
    int t = threadIdx.x;
    if (t < 128) red[t] = (t < blockIdx.x) ? g_bsum[t] : 0;
    __syncthreads();
    for (int o = 64; o > 0; o >>= 1) {
        if (t < o) red[t] += red[t + o];
        __syncthreads();
    }
    int add = red[0];
    int i = blockIdx.x * 1024 + t;
    if (i >= n) return;
    int d = g_degi[i];
    int inc = g_scan[i] + add;
    int off = inc - d;
    g_off[i] = off;
    g_cur[i] = off;
    g_dinv[i] = rsqrtf((float)d + 1.0f);
    if (i == n - 1) g_off[n] = inc;
}
__global__ void k_place(const int* __restrict__ row, const int* __restrict__ col, int E) {
    int e = blockIdx.x * blockDim.x + threadIdx.x;
    if (e >= E) return;
    int c = col[e];
    int p = atomicAdd(&g_cur[c], 1);
    g_csr[p] = row[e];
}

// ---------------------------------------------------------------------------
// MMA helpers
// ---------------------------------------------------------------------------
__device__ __forceinline__ void mma_bf16(float c[4], const uint32_t a[4], const uint32_t b[2]) {
    asm("mma.sync.aligned.m16n8k16.row.col.f32.bf16.bf16.f32 "
        "{%0,%1,%2,%3}, {%4,%5,%6,%7}, {%8,%9}, {%0,%1,%2,%3};"
        : "+f"(c[0]), "+f"(c[1]), "+f"(c[2]), "+f"(c[3])
        : "r"(a[0]), "r"(a[1]), "r"(a[2]), "r"(a[3]), "r"(b[0]), "r"(b[1]));
}
__device__ __forceinline__ void ldsm_x4(uint32_t& r0, uint32_t& r1, uint32_t& r2, uint32_t& r3,
                                        uint32_t addr) {
    asm volatile("ldmatrix.sync.aligned.m8n8.x4.shared.b16 {%0,%1,%2,%3}, [%4];"
                 : "=r"(r0), "=r"(r1), "=r"(r2), "=r"(r3) : "r"(addr));
}
__device__ __forceinline__ uint32_t pack_bf2(float x, float y) {
    __nv_bfloat162 p = __float22bfloat162_rn(make_float2(x, y));
    return *reinterpret_cast<uint32_t*>(&p);
}

// ---------------------------------------------------------------------------
// bf16 MMA GEMM (m16n8k16) with ldmatrix fragment loads.
//   C[M,Ncols] = A[M,K] @ B[Ncols,K]^T (fp32 inputs, bf16 conversion in smem)
//   MODE 0: C (f32) = v (+bias)(+relu)
//   MODE 1: gc<D: Cb (bf16x2) = dinv*v ; else C2 (z, f32) = v
//   MODE 2: gc<D: Cb (bf16x2) = dinv*v ; else (uint32_t*)C2 (z, bf16x2) = v
// ---------------------------------------------------------------------------
template<int BN, int WN, int MODE, bool RELU, bool HASB>
__global__ __launch_bounds__(256) void
k_mmab(const float* __restrict__ A, const float* __restrict__ B,
       const float* __restrict__ bias,
       float* __restrict__ C, float* __restrict__ C2,
       uint32_t* __restrict__ Cb,
       int M, int Ncols, int K, int D) {
    constexpr int BM = 128, BK = 32, BKP2 = 20;  // 16 pairs + pad 4
    constexpr int MT = 2, NT = WN / 8, NP = NT / 2;
    constexpr int AL = (BM * BK / 4) / 256;
    constexpr int BL = (BN * BK / 4) / 256;
    __shared__ uint32_t As[BM][BKP2];
    __shared__ uint32_t Bs[BN][BKP2];

    const int tid  = threadIdx.x;
    const int warp = tid >> 5, lane = tid & 31;
    const int grp  = lane >> 2, qid = lane & 3;
    const int wm0  = (warp & 3) * 32;
    const int wn0  = (warp >> 2) * WN;
    const int row0 = blockIdx.y * BM;
    const int col0 = blockIdx.x * BN;

    const int ldr = tid >> 3;          // 0..31
    const int ldc = (tid & 7) * 4;     // float column
    const int pc  = (tid & 7) * 2;     // pair column

    // ldmatrix source addresses (constant across k0 iterations)
    const int lr = lane & 7, lq = lane >> 3;
    uint32_t a_addr[MT], b_addr[NP];
#pragma unroll
    for (int i = 0; i < MT; i++)
        a_addr[i] = (uint32_t)__cvta_generic_to_shared(
            &As[wm0 + i * 16 + (lq & 1) * 8 + lr][(lq >> 1) * 4]);
#pragma unroll
    for (int j = 0; j < NP; j++)
        b_addr[j] = (uint32_t)__cvta_generic_to_shared(
            &Bs[wn0 + j * 16 + (lq >> 1) * 8 + lr][(lq & 1) * 4]);

    float acc[MT][NT][4];
#pragma unroll
    for (int i = 0; i < MT; i++)
#pragma unroll
        for (int j = 0; j < NT; j++)
#pragma unroll
            for (int q = 0; q < 4; q++) acc[i][j][q] = 0.0f;

    float4 pa[AL], pb[BL];

#pragma unroll
    for (int u = 0; u < AL; u++) {
        int gr = row0 + ldr + u * 32;
        pa[u] = make_float4(0.f, 0.f, 0.f, 0.f);
        if (gr < M) pa[u] = *(const float4*)(A + (size_t)gr * K + ldc);
    }
#pragma unroll
    for (int u = 0; u < BL; u++)
        pb[u] = *(const float4*)(B + (size_t)(col0 + ldr + u * 32) * K + ldc);

    for (int k0 = 0; k0 < K; k0 += BK) {
        __syncthreads();
#pragma unroll
        for (int u = 0; u < AL; u++) {
            As[ldr + u * 32][pc    ] = pack_bf2(pa[u].x, pa[u].y);
            As[ldr + u * 32][pc + 1] = pack_bf2(pa[u].z, pa[u].w);
        }
#pragma unroll
        for (int u = 0; u < BL; u++) {
            Bs[ldr + u * 32][pc    ] = pack_bf2(pb[u].x, pb[u].y);
            Bs[ldr + u * 32][pc + 1] = pack_bf2(pb[u].z, pb[u].w);
        }
        __syncthreads();

        if (k0 + BK < K) {
            int kn = k0 + BK;
#pragma unroll
            for (int u = 0; u < AL; u++) {
                int gr = row0 + ldr + u * 32;
                pa[u] = make_float4(0.f, 0.f, 0.f, 0.f);
                if (gr < M) pa[u] = *(const float4*)(A + (size_t)gr * K + kn + ldc);
            }
#pragma unroll
            for (int u = 0; u < BL; u++)
                pb[u] = *(const float4*)(B + (size_t)(col0 + ldr + u * 32) * K + kn + ldc);
        }

#pragma unroll
        for (int kk = 0; kk < BK / 16; kk++) {
            const uint32_t koff = kk * 32;   // 8 pairs = 32 bytes per k-chunk
            uint32_t af[MT][4], bf[NT][2];
#pragma unroll
            for (int i = 0; i < MT; i++)
                ldsm_x4(af[i][0], af[i][1], af[i][2], af[i][3], a_addr[i] + koff);
#pragma unroll
            for (int j = 0; j < NP; j++)
                ldsm_x4(bf[2 * j][0], bf[2 * j][1], bf[2 * j + 1][0], bf[2 * j + 1][1],
                        b_addr[j] + koff);
#pragma unroll
            for (int i = 0; i < MT; i++)
#pragma unroll
                for (int j = 0; j < NT; j++)
                    mma_bf16(acc[i][j], af[i], bf[j]);
        }
    }

#pragma unroll
    for (int i = 0; i < MT; i++) {
#pragma unroll
        for (int h = 0; h < 2; h++) {
            int gr = row0 + wm0 + i * 16 + grp + h * 8;
            if (gr >= M) continue;
            float di = (MODE != 0) ? g_dinv[gr] : 0.0f;
#pragma unroll
            for (int j = 0; j < NT; j++) {
                int gc = col0 + wn0 + j * 8 + 2 * qid;
                float v0 = acc[i][j][2 * h];
                float v1 = acc[i][j][2 * h + 1];
                if (MODE == 0) {
                    if (HASB) { v0 += bias[gc]; v1 += bias[gc + 1]; }
                    if (RELU) { v0 = fmaxf(v0, 0.f); v1 = fmaxf(v1, 0.f); }
                    *(float2*)(C + (size_t)gr * Ncols + gc) = make_float2(v0, v1);
                } else if (MODE == 1) {
                    if (gc < D) {
                        Cb[(size_t)gr * (D / 2) + gc / 2] = pack_bf2(di * v0, di * v1);
                    } else {
                        *(float2*)(C2 + (size_t)gr * D + gc - D) = make_float2(v0, v1);
                    }
                } else {
                    if (gc < D) {
                        Cb[(size_t)gr * (D / 2) + gc / 2] = pack_bf2(di * v0, di * v1);
                    } else {
                        ((uint32_t*)C2)[(size_t)gr * (D / 2) + (gc - D) / 2] = pack_bf2(v0, v1);
                    }
                }
            }
        }
    }
}

// ---------------------------------------------------------------------------
// Layer-1 CSR gather + fused Euler update (warp/node, lane = 4 cols)
// ---------------------------------------------------------------------------
__device__ __forceinline__ void acc_bf4(float& sx, float& sy, float& sz, float& sw, uint2 v) {
    __nv_bfloat162 q0 = *reinterpret_cast<__nv_bfloat162*>(&v.x);
    __nv_bfloat162 q1 = *reinterpret_cast<__nv_bfloat162*>(&v.y);
    float2 g0 = __bfloat1622float2(q0);
    float2 g1 = __bfloat1622float2(q1);
    sx += g0.x; sy += g0.y; sz += g1.x; sw += g1.y;
}

__global__ void k_gather1(const float* __restrict__ b1) {
    int n    = (blockIdx.x * blockDim.x + threadIdx.x) >> 5;
    int lane = threadIdx.x & 31;
    if (n >= N_NODES) return;

    const uint2* xb = (const uint2*)g_xw1b;
    int beg = g_off[n], end = g_off[n + 1];

    float sx, sy, sz, sw;
    { uint2 sv = xb[(size_t)n * 32 + lane];
      sx = sy = sz = sw = 0.0f;
      acc_bf4(sx, sy, sz, sw, sv); }

    for (int base = beg; base < end; base += 32) {
        int mye = base + lane;
        int r = (mye < end) ? g_csr[mye] : 0;
        int cnt = min(32, end - base);
        int j = 0;
        for (; j + 4 <= cnt; j += 4) {
            int r0 = __shfl_sync(0xffffffffu, r, j);
            int r1 = __shfl_sync(0xffffffffu, r, j + 1);
            int r2 = __shfl_sync(0xffffffffu, r, j + 2);
            int r3 = __shfl_sync(0xffffffffu, r, j + 3);
            uint2 v0 = xb[(size_t)r0 * 32 + lane];
            uint2 v1 = xb[(size_t)r1 * 32 + lane];
            uint2 v2 = xb[(size_t)r2 * 32 + lane];
            uint2 v3 = xb[(size_t)r3 * 32 + lane];
            acc_bf4(sx, sy, sz, sw, v0);
            acc_bf4(sx, sy, sz, sw, v1);
            acc_bf4(sx, sy, sz, sw, v2);
            acc_bf4(sx, sy, sz, sw, v3);
        }
        for (; j < cnt; j++) {
            int rr = __shfl_sync(0xffffffffu, r, j);
            acc_bf4(sx, sy, sz, sw, xb[(size_t)rr * 32 + lane]);
        }
    }

    float u = g_dinv[n];
    size_t i4 = (size_t)n * 32 + lane;
    uint2 zv = ((const uint2*)g_z1b)[i4];
    float2 za = __bfloat1622float2(*reinterpret_cast<__nv_bfloat162*>(&zv.x));
    float2 zb = __bfloat1622float2(*reinterpret_cast<__nv_bfloat162*>(&zv.y));
    float4 b = ((const float4*)b1)[lane];
    float4 h = ((const float4*)g_h1)[i4];
    h.x += EPS_F * tanhf(za.x + u * sx + b.x);
    h.y += EPS_F * tanhf(za.y + u * sy + b.y);
    h.z += EPS_F * tanhf(zb.x + u * sz + b.z);
    h.w += EPS_F * tanhf(zb.y + u * sw + b.w);
    ((float4*)g_h1)[i4] = h;
}

// ---------------------------------------------------------------------------
// Layer-2 gather (bf16) + fused update + log_softmax
//   Half-warp per node, per-half-warp shfl masks.
// ---------------------------------------------------------------------------
__global__ void k_gather2(const float* __restrict__ b2, float* __restrict__ out) {
    int n = (blockIdx.x * blockDim.x + threadIdx.x) >> 4;
    int l = threadIdx.x & 15;
    if (n >= N_NODES) return;

    const unsigned hm = 0xffffu << (threadIdx.x & 16);

    int beg = g_off[n], end = g_off[n + 1];

    float s0, s1;
    { uint32_t sv = g_xw2b[(size_t)n * 16 + l];
      __nv_bfloat162 sp = *reinterpret_cast<__nv_bfloat162*>(&sv);
      float2 sf = __bfloat1622float2(sp);
      s0 = sf.x; s1 = sf.y; }

    for (int base = beg; base < end; base += 16) {
        int mye = base + l;
        int r = (mye < end) ? g_csr[mye] : 0;
        int cnt = min(16, end - base);
        int j = 0;
        for (; j + 4 <= cnt; j += 4) {
            int rr[4];
#pragma unroll
            for (int q = 0; q < 4; q++) rr[q] = __shfl_sync(hm, r, j + q, 16);
            uint32_t a[4];
#pragma unroll
            for (int q = 0; q < 4; q++) a[q] = g_xw2b[(size_t)rr[q] * 16 + l];
#pragma unroll
            for (int q = 0; q < 4; q++) {
                float2 f = __bfloat1622float2(*reinterpret_cast<__nv_bfloat162*>(&a[q]));
                s0 += f.x; s1 += f.y;
            }
        }
        for (; j < cnt; j++) {
            int rr = __shfl_sync(hm, r, j, 16);
            uint32_t a = g_xw2b[(size_t)rr * 16 + l];
            float2 f = __bfloat1622float2(*reinterpret_cast<__nv_bfloat162*>(&a));
            s0 += f.x; s1 += f.y;
        }
    }

    float u = g_dinv[n];
    size_t base2 = (size_t)n * CLS + 2 * l;
    float2 z = *(const float2*)(g_z2 + base2);
    float2 h = *(const float2*)(g_h2 + base2);
    float2 b = *(const float2*)(b2 + 2 * l);
    float v0 = h.x + EPS_F * tanhf(z.x + u * s0 + b.x);
    float v1 = h.y + EPS_F * tanhf(z.y + u * s1 + b.y);
    float m = fmaxf(v0, v1);
#pragma unroll
    for (int o = 8; o > 0; o >>= 1) m = fmaxf(m, __shfl_xor_sync(hm, m, o, 16));
    float sum = expf(v0 - m) + expf(v1 - m);
#pragma unroll
    for (int o = 8; o > 0; o >>= 1) sum += __shfl_xor_sync(hm, sum, o, 16);
    float ls = logf(sum);
    *(float2*)(out + base2) = make_float2(v0 - m - ls, v1 - m - ls);
}

// ---------------------------------------------------------------------------
// Launch (single default stream; round-15 structure)
// ---------------------------------------------------------------------------
extern "C" void kernel_launch(void* const* d_in, const int* in_sizes, int n_in,
                              void* d_out, int out_size) {
    const float* x      = (const float*)d_in[0];
    const float* lin1_w = (const float*)d_in[1];
    const float* lin1_b = (const float*)d_in[2];
    const float* lin2_w = (const float*)d_in[3];
    const float* lin2_b = (const float*)d_in[4];
    const float* W1     = (const float*)d_in[5];
    const float* phi1   = (const float*)d_in[6];
    const float* b1     = (const float*)d_in[7];
    const float* W2     = (const float*)d_in[8];
    const float* phi2   = (const float*)d_in[9];
    const float* b2     = (const float*)d_in[10];
    const int*   ei     = (const int*)d_in[11];
    int E = in_sizes[11] / 2;
    const int* erow = ei;
    const int* ecol = ei + E;
    float* out = (float*)d_out;

    float *p_h1, *p_h2, *p_z2, *p_c1, *p_c2;
    uint32_t *p_xw1b, *p_z1b, *p_xw2b;
    cudaGetSymbolAddress((void**)&p_h1,   g_h1);
    cudaGetSymbolAddress((void**)&p_xw1b, g_xw1b);
    cudaGetSymbolAddress((void**)&p_z1b,  g_z1b);
    cudaGetSymbolAddress((void**)&p_h2,   g_h2);
    cudaGetSymbolAddress((void**)&p_xw2b, g_xw2b);
    cudaGetSymbolAddress((void**)&p_z2,   g_z2);
    cudaGetSymbolAddress((void**)&p_c1,   g_comb1);
    cudaGetSymbolAddress((void**)&p_c2,   g_comb2);

    const int TPB = 256;
    int mb128 = (N_NODES + 127) / 128;
    int scan_blocks = (N_NODES + 1023) / 1024;
    int warp_blocks  = (N_NODES * 32 + TPB - 1) / TPB;
    int hwarp_blocks = (N_NODES * 16 + TPB - 1) / TPB;

    // ---- prep: comb1 + comb2 + deg zero ----
    k_prep<<<(PREP_TOTAL + TPB - 1) / TPB, TPB>>>(W1, phi1, W2, phi2);

    // ---- CSR build ----
    k_deg_accum<<<(E + TPB - 1) / TPB, TPB>>>(ecol, E);
    k_scan1    <<<scan_blocks, 1024>>>(N_NODES);
    k_scan3    <<<scan_blocks, 1024>>>(N_NODES);
    k_place    <<<(E + TPB - 1) / TPB, TPB>>>(erow, ecol, E);

    // ---- h1 = relu(x @ lin1_w^T + lin1_b)   [N,128]  (bf16 MMA + ldmatrix) ----
    k_mmab<128, 64, 0, true, true>
        <<<dim3(1, mb128), 256>>>(x, lin1_w, lin1_b, p_h1, nullptr, nullptr, N_NODES, HID, F_IN, 0);

    // ---- (xws1_bf16 | z1_bf16) = h1 @ comb1^T   [N,256]  (MODE 2) ----
    k_mmab<128, 64, 2, false, false>
        <<<dim3(2, mb128), 256>>>(p_h1, p_c1, nullptr, nullptr, (float*)p_z1b, p_xw1b, N_NODES, 2 * HID, HID, HID);

    // ---- layer-1 gather + fused Euler update ----
    k_gather1<<<warp_blocks, TPB>>>(b1);

    // ---- h2 = h1 @ lin2_w^T + lin2_b   [N,32]  (bf16 MMA) ----
    k_mmab<32, 16, 0, false, true>
        <<<dim3(1, mb128), 256>>>(p_h1, lin2_w, lin2_b, p_h2, nullptr, nullptr, N_NODES, CLS, HID, 0);

    // ---- (xws2_bf16 | z2_f32) = h2 @ comb2^T   [N,64]  (MODE 1) ----
    k_mmab<64, 32, 1, false, false>
        <<<dim3(1, mb128), 256>>>(p_h2, p_c2, nullptr, nullptr, p_z2, p_xw2b, N_NODES, 2 * CLS, CLS, CLS);

    // ---- layer-2 gather + fused update + log_softmax ----
    k_gather2<<<hwarp_blocks, TPB>>>(b2, out);
}